// round 5
// baseline (speedup 1.0000x reference)
#include <cuda_runtime.h>
#include <cuda_bf16.h>
#include <cstdint>

// ---------------------------------------------------------------------------
// NodeUnpool via mma.sync (HMMA, bf16 3-product split), copy FUSED with GEMM:
//   out = h_full;  out[idx] = h_full[idx]@W1^T + b1 + h_sub@W2^T + b2
// C[M,256] = [h_full[idx] | h_sub] @ [W1 | W2]^T   (K = 512 concat)
// Grid = 3*tiles: bx%3<2 -> GEMM tile CTA, bx%3==2 -> copy CTA that copies
// only rows NOT in idx (byte mask), so writes are disjoint and race-free.
// ---------------------------------------------------------------------------

#define DIM      256
#define BM       128
#define BN       128
#define KC       64
#define THREADS  256
#define STRIDE_B 144            // smem row stride in bytes (72 halves)

// smem layout (bytes)
#define SM_ROWIDX 0             // int[128]
#define SM_BIAS   512           // float[128]
#define SM_AH     1024          // [128][72] bf16 = 18432
#define SM_AL     (SM_AH + 18432)
#define SM_B0     (SM_AL + 18432)     // B stages start: 37888
#define B_STAGE   36864               // Bh(18432)+Bl(18432) per stage
#define B_LOFF    18432
#define SM_TOTAL  (SM_B0 + 2 * B_STAGE)   // 111616

#define MASK_CAP  (2u << 20)

__device__ int g_idx_is64;
__device__ __align__(16) __nv_bfloat16 g_Bh[256 * 512];   // [n][kcat]
__device__ __align__(16) __nv_bfloat16 g_Bl[256 * 512];
__device__ __align__(16) unsigned char g_mask[MASK_CAP];  // 1 = pooled row

// ---------------- helpers ----------------
__device__ __forceinline__ uint32_t smem_u32(const void* p) {
    uint32_t a;
    asm("{ .reg .u64 t; cvta.to.shared.u64 t, %1; cvt.u32.u64 %0, t; }"
        : "=r"(a) : "l"(p));
    return a;
}
__device__ __forceinline__ void cp_async16(uint32_t dst, const void* src) {
    asm volatile("cp.async.cg.shared.global [%0], [%1], 16;"
                 :: "r"(dst), "l"(src) : "memory");
}
__device__ __forceinline__ void cp_commit() {
    asm volatile("cp.async.commit_group;" ::: "memory");
}
__device__ __forceinline__ void cp_wait0() {
    asm volatile("cp.async.wait_group 0;" ::: "memory");
}
__device__ __forceinline__ void ldsm4(uint32_t* r, uint32_t addr) {
    asm volatile("ldmatrix.sync.aligned.m8n8.x4.shared.b16 {%0,%1,%2,%3}, [%4];"
                 : "=r"(r[0]), "=r"(r[1]), "=r"(r[2]), "=r"(r[3]) : "r"(addr));
}
__device__ __forceinline__ uint32_t lds32(uint32_t addr) {
    uint32_t v;
    asm volatile("ld.shared.b32 %0, [%1];" : "=r"(v) : "r"(addr));
    return v;
}
__device__ __forceinline__ void mma16816(float* d, const uint32_t* a,
                                         uint32_t b0, uint32_t b1) {
    asm volatile(
        "mma.sync.aligned.m16n8k16.row.col.f32.bf16.bf16.f32 "
        "{%0,%1,%2,%3}, {%4,%5,%6,%7}, {%8,%9}, {%0,%1,%2,%3};"
        : "+f"(d[0]), "+f"(d[1]), "+f"(d[2]), "+f"(d[3])
        : "r"(a[0]), "r"(a[1]), "r"(a[2]), "r"(a[3]), "r"(b0), "r"(b1));
}

// ---------------- idx dtype detection ----------------
__device__ __forceinline__ long long load_idx(const void* idx, int r, int is64) {
    if (is64) return reinterpret_cast<const long long*>(idx)[r];
    return (long long)reinterpret_cast<const int*>(idx)[r];
}
__global__ void detect_idx_kernel(const void* idx, int Mrows, long long Nfull) {
    const long long* p64 = reinterpret_cast<const long long*>(idx);
    int n = Mrows / 2;
    if (n > 8) n = 8;
    bool ok64 = (n > 0);
    for (int i = 0; i < n; ++i) {
        long long v = p64[i];
        if (v < 0 || v >= Nfull) { ok64 = false; break; }
    }
    g_idx_is64 = ok64 ? 1 : 0;
}

// ---------------- mask clear / set ----------------
__global__ void clear_mask(int nWords) {      // uint4 words
    int t = blockIdx.x * blockDim.x + threadIdx.x;
    uint4* p = reinterpret_cast<uint4*>(g_mask);
    if (t < nWords) p[t] = make_uint4(0, 0, 0, 0);
}
__global__ void set_mask(const void* __restrict__ idx, int Mrows) {
    int t = blockIdx.x * blockDim.x + threadIdx.x;
    if (t < Mrows) {
        long long g = load_idx(idx, t, g_idx_is64);
        g_mask[g] = 1;
    }
}

// ---------------- W -> bf16 hi/lo, [n][kcat] ----------------
__global__ void convert_W(const float* __restrict__ W1, const float* __restrict__ W2) {
    int t = blockIdx.x * blockDim.x + threadIdx.x;   // 256*512
    if (t >= 256 * 512) return;
    int n    = t >> 9;
    int kcat = t & 511;
    float x = (kcat < DIM) ? W1[n * DIM + kcat] : W2[n * DIM + (kcat - DIM)];
    __nv_bfloat16 h = __float2bfloat16(x);
    __nv_bfloat16 l = __float2bfloat16(x - __bfloat162float(h));
    g_Bh[t] = h;
    g_Bl[t] = l;
}

// ---------------- fused GEMM + masked copy ----------------
__global__ __launch_bounds__(THREADS)
void fused_gemm_copy(const float* __restrict__ h_full,
                     const float* __restrict__ h_sub,
                     const float* __restrict__ b1,
                     const float* __restrict__ b2,
                     const void*  __restrict__ idx,
                     float* __restrict__ out,
                     int Mrows, int Nfull, int nTiles)
{
    extern __shared__ __align__(16) char smem[];
    const int tid = threadIdx.x;
    const int bx  = blockIdx.x;
    const int grp = bx / 3;
    const int rem = bx - grp * 3;

    // ================= copy role =================
    if (rem == 2) {
        const int nCopy = nTiles;                 // copy CTA count
        const float4* in4  = reinterpret_cast<const float4*>(h_full);
        float4*       out4 = reinterpret_cast<float4*>(out);
        const size_t total = (size_t)Nfull * (DIM / 4);   // float4 count
        const size_t step  = (size_t)nCopy * THREADS;
        for (size_t g = (size_t)grp * THREADS + tid; g < total; g += step) {
            int r = (int)(g >> 6);                // DIM/4 = 64 float4 per row
            if (!g_mask[r]) out4[g] = in4[g];
        }
        return;
    }

    // ================= GEMM role =================
    const uint32_t sbase = smem_u32(smem);
    const int gemmId = grp * 2 + rem;             // 0 .. 2*nTiles-1
    const int wid   = tid >> 5;
    const int lid   = tid & 31;
    const int tileM = (gemmId >> 1) * BM;
    const int nBase = (gemmId & 1) * BN;
    const int warpM = (wid & 3) * 32;
    const int warpN = (wid >> 2) * 64;

    int*   rowidx = (int*)(smem + SM_ROWIDX);
    float* biasS  = (float*)(smem + SM_BIAS);

    const int is64 = g_idx_is64;
    if (tid < BM) {
        int m = tileM + tid;
        rowidx[tid] = (m < Mrows) ? (int)load_idx(idx, m, is64) : 0;
        biasS[tid]  = b1[nBase + tid] + b2[nBase + tid];
    }
    __syncthreads();

    // ---- B stage fill via cp.async (chunk c -> stage st)
    auto issueB = [&](int c, int st) {
        uint32_t dbase = sbase + SM_B0 + st * B_STAGE;
#pragma unroll
        for (int j = 0; j < 4; ++j) {
            int id  = tid + j * THREADS;     // 0..1023
            int row = id >> 3;               // 0..127
            int seg = id & 7;                // 16B segment
            uint32_t dst = dbase + row * STRIDE_B + seg * 16;
            size_t srcOff = (((size_t)(nBase + row) << 9) + c * KC + seg * 8) * 2;
            cp_async16(dst,          (const char*)g_Bh + srcOff);
            cp_async16(dst + B_LOFF, (const char*)g_Bl + srcOff);
        }
    };

    // ---- A chunk gather into regs
    auto loadA = [&](float4* dst, int c) {
        const bool fromFull = (c < 4);
        const int  kb = (c & 3) * KC;
#pragma unroll
        for (int j = 0; j < 8; ++j) {
            int id = tid + j * THREADS;      // 0..2047
            int r  = id >> 4;                // 0..127
            int c4 = (id & 15) << 2;         // 0..60
            const float* src;
            if (fromFull) {
                src = h_full + (size_t)rowidx[r] * DIM;
            } else {
                int m = tileM + r;
                if (m >= Mrows) m = Mrows - 1;
                src = h_sub + (size_t)m * DIM;
            }
            dst[j] = *(const float4*)(src + kb + c4);
        }
    };

    // ---- A regs -> bf16 hi/lo smem
    auto storeA = [&](const float4* v) {
#pragma unroll
        for (int j = 0; j < 8; ++j) {
            int id = tid + j * THREADS;
            int r  = id >> 4;
            int c4 = (id & 15) << 2;
            float4 q = v[j];
            __nv_bfloat16 hx = __float2bfloat16(q.x);
            __nv_bfloat16 hy = __float2bfloat16(q.y);
            __nv_bfloat16 hz = __float2bfloat16(q.z);
            __nv_bfloat16 hw = __float2bfloat16(q.w);
            __nv_bfloat162 h01; h01.x = hx; h01.y = hy;
            __nv_bfloat162 h23; h23.x = hz; h23.y = hw;
            __nv_bfloat162 l01, l23;
            l01.x = __float2bfloat16(q.x - __bfloat162float(hx));
            l01.y = __float2bfloat16(q.y - __bfloat162float(hy));
            l23.x = __float2bfloat16(q.z - __bfloat162float(hz));
            l23.y = __float2bfloat16(q.w - __bfloat162float(hw));
            uint32_t off = r * STRIDE_B + c4 * 2;
            *(uint2*)(smem + SM_AH + off) =
                make_uint2(*(uint32_t*)&h01, *(uint32_t*)&h23);
            *(uint2*)(smem + SM_AL + off) =
                make_uint2(*(uint32_t*)&l01, *(uint32_t*)&l23);
        }
    };

    float acc[2][8][4];
#pragma unroll
    for (int mt = 0; mt < 2; ++mt)
#pragma unroll
        for (int nt = 0; nt < 8; ++nt)
#pragma unroll
            for (int q = 0; q < 4; ++q) acc[mt][nt][q] = 0.f;

    // ---- compute one KC=64 chunk from stage st
    auto compute = [&](int st) {
        const uint32_t aH = sbase + SM_AH;
        const uint32_t bB = sbase + SM_B0 + st * B_STAGE;
#pragma unroll
        for (int kk = 0; kk < 4; ++kk) {
            uint32_t ah[2][4], al[2][4];
#pragma unroll
            for (int mt = 0; mt < 2; ++mt) {
                uint32_t ra = (uint32_t)(warpM + mt * 16 + (lid & 15)) * STRIDE_B
                            + (kk * 16 + (lid >> 4) * 8) * 2;
                ldsm4(ah[mt], aH + ra);
                ldsm4(al[mt], aH + 18432 + ra);
            }
#pragma unroll
            for (int nt = 0; nt < 8; ++nt) {
                uint32_t rb = bB + (uint32_t)(warpN + nt * 8 + (lid >> 2)) * STRIDE_B
                            + (kk * 16 + (lid & 3) * 2) * 2;
                uint32_t bh0 = lds32(rb),          bh1 = lds32(rb + 16);
                uint32_t bl0 = lds32(rb + B_LOFF), bl1 = lds32(rb + B_LOFF + 16);
#pragma unroll
                for (int mt = 0; mt < 2; ++mt) {
                    mma16816(acc[mt][nt], ah[mt], bh0, bh1);
                    mma16816(acc[mt][nt], ah[mt], bl0, bl1);
                    mma16816(acc[mt][nt], al[mt], bh0, bh1);
                }
            }
        }
    };

    // ---- prologue: chunk 0
    float4 aPre[8];
    issueB(0, 0);
    cp_commit();
    loadA(aPre, 0);
    storeA(aPre);
    cp_wait0();
    __syncthreads();

    // ---- main loop over 8 K-chunks (2 passes x 4)
#pragma unroll 1
    for (int c = 0; c < 8; ++c) {
        const int st = c & 1;
        if (c < 7) {
            issueB(c + 1, st ^ 1);
            cp_commit();
            loadA(aPre, c + 1);
        }
        compute(st);
        __syncthreads();                 // everyone done reading A smem + B[st]
        if (c < 7) {
            storeA(aPre);
            cp_wait0();
        }
        __syncthreads();                 // next A/B staged
    }

    // ---- epilogue: bias add + scatter from register accumulators
    {
        const int r0 = lid >> 2;            // 0..7
        const int nc = (lid & 3) * 2;       // 0,2,4,6
#pragma unroll
        for (int mt = 0; mt < 2; ++mt) {
#pragma unroll
            for (int half = 0; half < 2; ++half) {
                int row = warpM + mt * 16 + r0 + half * 8;   // local 0..127
                int mg  = tileM + row;
                if (mg < Mrows) {
                    float* orow = out + (size_t)rowidx[row] * DIM + nBase + warpN;
#pragma unroll
                    for (int nt = 0; nt < 8; ++nt) {
                        float2 bv = *(const float2*)&biasS[warpN + nt * 8 + nc];
                        float2 v;
                        v.x = acc[mt][nt][half * 2 + 0] + bv.x;
                        v.y = acc[mt][nt][half * 2 + 1] + bv.y;
                        *(float2*)(orow + nt * 8 + nc) = v;
                    }
                }
            }
        }
    }
}

// ---------------- launch ----------------
extern "C" void kernel_launch(void* const* d_in, const int* in_sizes, int n_in,
                              void* d_out, int out_size) {
    const float* h_full = (const float*)d_in[0];
    const float* h_sub  = (const float*)d_in[1];
    const float* W1     = (const float*)d_in[2];
    const float* b1     = (const float*)d_in[3];
    const float* W2     = (const float*)d_in[4];
    const float* b2     = (const float*)d_in[5];
    const void*  idx    = d_in[6];
    float*       out    = (float*)d_out;

    const int dim   = in_sizes[3];
    const int Mrows = in_sizes[1] / dim;
    const int Nfull = in_sizes[0] / dim;

    cudaFuncSetAttribute(fused_gemm_copy,
                         cudaFuncAttributeMaxDynamicSharedMemorySize, SM_TOTAL);

    detect_idx_kernel<<<1, 1>>>(idx, Mrows, (long long)Nfull);
    convert_W<<<(256 * 512 + 255) / 256, 256>>>(W1, W2);

    // mask: clear (uint4 granularity) then set pooled rows
    const int maskWords = (Nfull + 15) / 16;
    clear_mask<<<(maskWords + 255) / 256, 256>>>(maskWords);
    set_mask<<<(Mrows + 255) / 256, 256>>>(idx, Mrows);

    const int tiles = (Mrows + BM - 1) / BM;
    fused_gemm_copy<<<tiles * 3, THREADS, SM_TOTAL>>>(
        h_full, h_sub, b1, b2, idx, out, Mrows, Nfull, tiles);
}

// round 6
// speedup vs baseline: 1.8288x; 1.8288x over previous
#include <cuda_runtime.h>
#include <cuda_bf16.h>
#include <cstdint>

// ---------------------------------------------------------------------------
// NodeUnpool via mma.sync (HMMA, bf16 3-product split):
//   out = h_full;  out[idx] = h_full[idx]@W1^T + b1 + h_sub@W2^T + b2
// C[M,256] = [h_full[idx] | h_sub] @ [W1 | W2]^T   (K = 512 concat)
//
// R6: masked copy (skips pooled rows, disjoint from GEMM scatter) runs on a
// SECOND stream via capture fork-join, overlapping the GEMM. Copy kernel has
// no smem / few regs so it co-resides with GEMM CTAs.
// ---------------------------------------------------------------------------

#define DIM      256
#define BM       128
#define BN       128
#define KC       64
#define THREADS  256
#define STRIDE_B 144            // smem row stride in bytes (72 halves)

// smem layout (bytes)
#define SM_ROWIDX 0             // int[128]
#define SM_BIAS   512           // float[128]
#define SM_AH     1024          // [128][72] bf16 = 18432
#define SM_AL     (SM_AH + 18432)
#define SM_B0     (SM_AL + 18432)     // B stages start: 37888
#define B_STAGE   36864               // Bh(18432)+Bl(18432) per stage
#define B_LOFF    18432
#define SM_TOTAL  (SM_B0 + 2 * B_STAGE)   // 111616

#define MASK_CAP  (2u << 20)

__device__ int g_idx_is64;
__device__ __align__(16) __nv_bfloat16 g_Bh[256 * 512];   // [n][kcat]
__device__ __align__(16) __nv_bfloat16 g_Bl[256 * 512];
__device__ __align__(16) unsigned char g_mask[MASK_CAP];  // 1 = pooled row

// ---------------- helpers ----------------
__device__ __forceinline__ uint32_t smem_u32(const void* p) {
    uint32_t a;
    asm("{ .reg .u64 t; cvta.to.shared.u64 t, %1; cvt.u32.u64 %0, t; }"
        : "=r"(a) : "l"(p));
    return a;
}
__device__ __forceinline__ void cp_async16(uint32_t dst, const void* src) {
    asm volatile("cp.async.cg.shared.global [%0], [%1], 16;"
                 :: "r"(dst), "l"(src) : "memory");
}
__device__ __forceinline__ void cp_commit() {
    asm volatile("cp.async.commit_group;" ::: "memory");
}
__device__ __forceinline__ void cp_wait0() {
    asm volatile("cp.async.wait_group 0;" ::: "memory");
}
__device__ __forceinline__ void ldsm4(uint32_t* r, uint32_t addr) {
    asm volatile("ldmatrix.sync.aligned.m8n8.x4.shared.b16 {%0,%1,%2,%3}, [%4];"
                 : "=r"(r[0]), "=r"(r[1]), "=r"(r[2]), "=r"(r[3]) : "r"(addr));
}
__device__ __forceinline__ uint32_t lds32(uint32_t addr) {
    uint32_t v;
    asm volatile("ld.shared.b32 %0, [%1];" : "=r"(v) : "r"(addr));
    return v;
}
__device__ __forceinline__ void mma16816(float* d, const uint32_t* a,
                                         uint32_t b0, uint32_t b1) {
    asm volatile(
        "mma.sync.aligned.m16n8k16.row.col.f32.bf16.bf16.f32 "
        "{%0,%1,%2,%3}, {%4,%5,%6,%7}, {%8,%9}, {%0,%1,%2,%3};"
        : "+f"(d[0]), "+f"(d[1]), "+f"(d[2]), "+f"(d[3])
        : "r"(a[0]), "r"(a[1]), "r"(a[2]), "r"(a[3]), "r"(b0), "r"(b1));
}

// ---------------- idx dtype detection ----------------
__device__ __forceinline__ long long load_idx(const void* idx, int r, int is64) {
    if (is64) return reinterpret_cast<const long long*>(idx)[r];
    return (long long)reinterpret_cast<const int*>(idx)[r];
}
__global__ void detect_idx_kernel(const void* idx, int Mrows, long long Nfull) {
    const long long* p64 = reinterpret_cast<const long long*>(idx);
    int n = Mrows / 2;
    if (n > 8) n = 8;
    bool ok64 = (n > 0);
    for (int i = 0; i < n; ++i) {
        long long v = p64[i];
        if (v < 0 || v >= Nfull) { ok64 = false; break; }
    }
    g_idx_is64 = ok64 ? 1 : 0;
}

// ---------------- mask clear / set ----------------
__global__ void clear_mask(int nWords) {      // uint4 words
    int t = blockIdx.x * blockDim.x + threadIdx.x;
    uint4* p = reinterpret_cast<uint4*>(g_mask);
    if (t < nWords) p[t] = make_uint4(0, 0, 0, 0);
}
__global__ void set_mask(const void* __restrict__ idx, int Mrows) {
    int t = blockIdx.x * blockDim.x + threadIdx.x;
    if (t < Mrows) {
        long long g = load_idx(idx, t, g_idx_is64);
        g_mask[g] = 1;
    }
}

// ---------------- W -> bf16 hi/lo, [n][kcat] ----------------
__global__ void convert_W(const float* __restrict__ W1, const float* __restrict__ W2) {
    int t = blockIdx.x * blockDim.x + threadIdx.x;   // 256*512
    if (t >= 256 * 512) return;
    int n    = t >> 9;
    int kcat = t & 511;
    float x = (kcat < DIM) ? W1[n * DIM + kcat] : W2[n * DIM + (kcat - DIM)];
    __nv_bfloat16 h = __float2bfloat16(x);
    __nv_bfloat16 l = __float2bfloat16(x - __bfloat162float(h));
    g_Bh[t] = h;
    g_Bl[t] = l;
}

// ---------------- masked row copy (skips pooled rows) ----------------
__global__ __launch_bounds__(256)
void masked_copy(const float* __restrict__ h_full,
                 float* __restrict__ out, int Nfull)
{
    // one warp-row = 64 float4 per node row; thread t covers element (g)
    const float4* in4  = reinterpret_cast<const float4*>(h_full);
    float4*       out4 = reinterpret_cast<float4*>(out);
    const size_t total = (size_t)Nfull * (DIM / 4);
    const size_t step  = (size_t)gridDim.x * blockDim.x;
    size_t g = (size_t)blockIdx.x * blockDim.x + threadIdx.x;
#pragma unroll 4
    for (; g < total; g += step) {
        int r = (int)(g >> 6);
        if (!g_mask[r]) out4[g] = in4[g];
    }
}

// ---------------- main GEMM ----------------
__global__ __launch_bounds__(THREADS)
void merge_gemm_mma(const float* __restrict__ h_full,
                    const float* __restrict__ h_sub,
                    const float* __restrict__ b1,
                    const float* __restrict__ b2,
                    const void*  __restrict__ idx,
                    float* __restrict__ out,
                    int Mrows)
{
    extern __shared__ __align__(16) char smem[];
    const uint32_t sbase = smem_u32(smem);

    const int tid   = threadIdx.x;
    const int wid   = tid >> 5;
    const int lid   = tid & 31;
    const int tileM = blockIdx.x * BM;
    const int nBase = blockIdx.y * BN;
    const int warpM = (wid & 3) * 32;
    const int warpN = (wid >> 2) * 64;

    int*   rowidx = (int*)(smem + SM_ROWIDX);
    float* biasS  = (float*)(smem + SM_BIAS);

    const int is64 = g_idx_is64;
    if (tid < BM) {
        int m = tileM + tid;
        rowidx[tid] = (m < Mrows) ? (int)load_idx(idx, m, is64) : 0;
        biasS[tid]  = b1[nBase + tid] + b2[nBase + tid];
    }
    __syncthreads();

    auto issueB = [&](int c, int st) {
        uint32_t dbase = sbase + SM_B0 + st * B_STAGE;
#pragma unroll
        for (int j = 0; j < 4; ++j) {
            int id  = tid + j * THREADS;     // 0..1023
            int row = id >> 3;               // 0..127
            int seg = id & 7;                // 16B segment
            uint32_t dst = dbase + row * STRIDE_B + seg * 16;
            size_t srcOff = (((size_t)(nBase + row) << 9) + c * KC + seg * 8) * 2;
            cp_async16(dst,          (const char*)g_Bh + srcOff);
            cp_async16(dst + B_LOFF, (const char*)g_Bl + srcOff);
        }
    };

    auto loadA = [&](float4* dst, int c) {
        const bool fromFull = (c < 4);
        const int  kb = (c & 3) * KC;
#pragma unroll
        for (int j = 0; j < 8; ++j) {
            int id = tid + j * THREADS;      // 0..2047
            int r  = id >> 4;                // 0..127
            int c4 = (id & 15) << 2;         // 0..60
            const float* src;
            if (fromFull) {
                src = h_full + (size_t)rowidx[r] * DIM;
            } else {
                int m = tileM + r;
                if (m >= Mrows) m = Mrows - 1;
                src = h_sub + (size_t)m * DIM;
            }
            dst[j] = *(const float4*)(src + kb + c4);
        }
    };

    auto storeA = [&](const float4* v) {
#pragma unroll
        for (int j = 0; j < 8; ++j) {
            int id = tid + j * THREADS;
            int r  = id >> 4;
            int c4 = (id & 15) << 2;
            float4 q = v[j];
            __nv_bfloat16 hx = __float2bfloat16(q.x);
            __nv_bfloat16 hy = __float2bfloat16(q.y);
            __nv_bfloat16 hz = __float2bfloat16(q.z);
            __nv_bfloat16 hw = __float2bfloat16(q.w);
            __nv_bfloat162 h01; h01.x = hx; h01.y = hy;
            __nv_bfloat162 h23; h23.x = hz; h23.y = hw;
            __nv_bfloat162 l01, l23;
            l01.x = __float2bfloat16(q.x - __bfloat162float(hx));
            l01.y = __float2bfloat16(q.y - __bfloat162float(hy));
            l23.x = __float2bfloat16(q.z - __bfloat162float(hz));
            l23.y = __float2bfloat16(q.w - __bfloat162float(hw));
            uint32_t off = r * STRIDE_B + c4 * 2;
            *(uint2*)(smem + SM_AH + off) =
                make_uint2(*(uint32_t*)&h01, *(uint32_t*)&h23);
            *(uint2*)(smem + SM_AL + off) =
                make_uint2(*(uint32_t*)&l01, *(uint32_t*)&l23);
        }
    };

    float acc[2][8][4];
#pragma unroll
    for (int mt = 0; mt < 2; ++mt)
#pragma unroll
        for (int nt = 0; nt < 8; ++nt)
#pragma unroll
            for (int q = 0; q < 4; ++q) acc[mt][nt][q] = 0.f;

    auto compute = [&](int st) {
        const uint32_t aH = sbase + SM_AH;
        const uint32_t bB = sbase + SM_B0 + st * B_STAGE;
#pragma unroll
        for (int kk = 0; kk < 4; ++kk) {
            uint32_t ah[2][4], al[2][4];
#pragma unroll
            for (int mt = 0; mt < 2; ++mt) {
                uint32_t ra = (uint32_t)(warpM + mt * 16 + (lid & 15)) * STRIDE_B
                            + (kk * 16 + (lid >> 4) * 8) * 2;
                ldsm4(ah[mt], aH + ra);
                ldsm4(al[mt], aH + 18432 + ra);
            }
#pragma unroll
            for (int nt = 0; nt < 8; ++nt) {
                uint32_t rb = bB + (uint32_t)(warpN + nt * 8 + (lid >> 2)) * STRIDE_B
                            + (kk * 16 + (lid & 3) * 2) * 2;
                uint32_t bh0 = lds32(rb),          bh1 = lds32(rb + 16);
                uint32_t bl0 = lds32(rb + B_LOFF), bl1 = lds32(rb + B_LOFF + 16);
#pragma unroll
                for (int mt = 0; mt < 2; ++mt) {
                    mma16816(acc[mt][nt], ah[mt], bh0, bh1);
                    mma16816(acc[mt][nt], ah[mt], bl0, bl1);
                    mma16816(acc[mt][nt], al[mt], bh0, bh1);
                }
            }
        }
    };

    // prologue: chunk 0
    float4 aPre[8];
    issueB(0, 0);
    cp_commit();
    loadA(aPre, 0);
    storeA(aPre);
    cp_wait0();
    __syncthreads();

#pragma unroll 1
    for (int c = 0; c < 8; ++c) {
        const int st = c & 1;
        if (c < 7) {
            issueB(c + 1, st ^ 1);
            cp_commit();
            loadA(aPre, c + 1);
        }
        compute(st);
        __syncthreads();
        if (c < 7) {
            storeA(aPre);
            cp_wait0();
        }
        __syncthreads();
    }

    // epilogue: bias add + scatter from register accumulators
    {
        const int r0 = lid >> 2;
        const int nc = (lid & 3) * 2;
#pragma unroll
        for (int mt = 0; mt < 2; ++mt) {
#pragma unroll
            for (int half = 0; half < 2; ++half) {
                int row = warpM + mt * 16 + r0 + half * 8;
                int mg  = tileM + row;
                if (mg < Mrows) {
                    float* orow = out + (size_t)rowidx[row] * DIM + nBase + warpN;
#pragma unroll
                    for (int nt = 0; nt < 8; ++nt) {
                        float2 bv = *(const float2*)&biasS[warpN + nt * 8 + nc];
                        float2 v;
                        v.x = acc[mt][nt][half * 2 + 0] + bv.x;
                        v.y = acc[mt][nt][half * 2 + 1] + bv.y;
                        *(float2*)(orow + nt * 8 + nc) = v;
                    }
                }
            }
        }
    }
}

// ---------------- launch ----------------
extern "C" void kernel_launch(void* const* d_in, const int* in_sizes, int n_in,
                              void* d_out, int out_size) {
    const float* h_full = (const float*)d_in[0];
    const float* h_sub  = (const float*)d_in[1];
    const float* W1     = (const float*)d_in[2];
    const float* b1     = (const float*)d_in[3];
    const float* W2     = (const float*)d_in[4];
    const float* b2     = (const float*)d_in[5];
    const void*  idx    = d_in[6];
    float*       out    = (float*)d_out;

    const int dim   = in_sizes[3];
    const int Mrows = in_sizes[1] / dim;
    const int Nfull = in_sizes[0] / dim;

    // one-time host-side resources (created on the uncaptured correctness call)
    static cudaStream_t sCopy = nullptr;
    static cudaEvent_t  evFork = nullptr, evJoin = nullptr;
    if (!sCopy) {
        cudaStreamCreateWithFlags(&sCopy, cudaStreamNonBlocking);
        cudaEventCreateWithFlags(&evFork, cudaEventDisableTiming);
        cudaEventCreateWithFlags(&evJoin, cudaEventDisableTiming);
    }

    cudaFuncSetAttribute(merge_gemm_mma,
                         cudaFuncAttributeMaxDynamicSharedMemorySize, SM_TOTAL);

    // prep (stream 0): dtype detect, W split, mask build
    detect_idx_kernel<<<1, 1>>>(idx, Mrows, (long long)Nfull);
    convert_W<<<(256 * 512 + 255) / 256, 256>>>(W1, W2);
    const int maskWords = (Nfull + 15) / 16;
    clear_mask<<<(maskWords + 255) / 256, 256>>>(maskWords);
    set_mask<<<(Mrows + 255) / 256, 256>>>(idx, Mrows);

    // fork: masked copy on sCopy, GEMM on stream 0 (writes are disjoint)
    cudaEventRecord(evFork, 0);
    cudaStreamWaitEvent(sCopy, evFork, 0);

    masked_copy<<<2048, 256, 0, sCopy>>>(h_full, out, Nfull);

    const int tiles = (Mrows + BM - 1) / BM;
    dim3 grid((unsigned)tiles, (unsigned)(dim / BN));
    merge_gemm_mma<<<grid, THREADS, SM_TOTAL>>>(h_full, h_sub, b1, b2, idx,
                                                out, Mrows);

    // join
    cudaEventRecord(evJoin, sCopy);
    cudaStreamWaitEvent(0, evJoin, 0);
}